// round 7
// baseline (speedup 1.0000x reference)
#include <cuda_runtime.h>

// Retrace: B=2048, T=512, D=16 (fp32).
// Segmented affine scan, vectorized float4 across d (4 chains/thread):
//   segment summary: carry_out = A*x + B,  loss_seg(x) = sdd - 2x*sAd + x^2*sAA
// Phase 2 chains segments (x <- A*x + B), sums quadratics, reduces to the mean.
//
// Inputs (metadata order):
//   0: Q [B,T,D]  1: expected_target_Q [B,T,D]  2: target_Q [B,T,D]
//   3: rewards [B,T,D]  4: target_policy_probs [B,T,D]  5: behaviour_policy_probs [B,T]
// Output: scalar fp32 = mean((Q[:, :-1] - q_ret)^2)

#define T_DIM 512
#define D_DIM 16
#define GAMMA 0.99f
#define BLOCK 128
#define SEG 16
#define SEGLEN 32                        // 511 = 16*32 - 1 (last segment: 31 steps)
#define NCHAINS (2048 * 16)              // 32768
#define NCG (NCHAINS / 4)                // 8192 chain-groups (float4 across d)
#define NBLK1 ((NCG * SEG) / BLOCK)      // 1024
#define NBLK2 (NCHAINS / BLOCK)          // 256

__device__ float g_sAA[SEG * NCHAINS];
__device__ float g_sAd[SEG * NCHAINS];
__device__ float g_sdd[SEG * NCHAINS];
__device__ float g_A  [SEG * NCHAINS];
__device__ float g_B  [SEG * NCHAINS];
__device__ float g_partials[NBLK2];
__device__ unsigned int g_ticket;        // zero-init; reset by finalizer each launch

// One recurrence step for 4 chains held as float4 lanes.
__device__ __forceinline__ void step4(const float4 r, const float4 qv, const float4 e,
                                      const float4 tq, const float4 tp, const float bp,
                                      float4& A, float4& Bv,
                                      float4& sAA, float4& sAd, float4& sdd)
{
#define ONE_LANE(X)                                                        \
    {                                                                      \
        float c  = __expf(fminf(tp.X - bp, 0.0f));                         \
        float m  = GAMMA * c;                                              \
        Bv.X = fmaf(m, Bv.X - tq.X, fmaf(GAMMA, e.X, r.X));                \
        A.X  = m * A.X;                                                    \
        float dv = qv.X - Bv.X;                                            \
        sdd.X = fmaf(dv, dv, sdd.X);                                       \
        sAd.X = fmaf(A.X, dv, sAd.X);                                      \
        sAA.X = fmaf(A.X, A.X, sAA.X);                                     \
    }
    ONE_LANE(x) ONE_LANE(y) ONE_LANE(z) ONE_LANE(w)
#undef ONE_LANE
}

// ---------------- Phase 1: per-(chain-group, segment) affine summary ----------------
__global__ __launch_bounds__(BLOCK)
void retrace_seg(const float* __restrict__ Q,
                 const float* __restrict__ E,
                 const float* __restrict__ TQ,
                 const float* __restrict__ R,
                 const float* __restrict__ TPP,
                 const float* __restrict__ BPP)
{
    const int tid = blockIdx.x * BLOCK + threadIdx.x;
    const int cg  = tid & (NCG - 1);            // chain-group id (d4 fastest -> coalesced)
    const int s   = tid >> 13;                  // segment id, 0..15
    const int b   = cg >> 2;
    const int d0  = (cg & 3) * 4;

    const int lo = s * SEGLEN;
    const int hi = (s == SEG - 1) ? (T_DIM - 2) : (lo + SEGLEN - 1);
    const int n  = hi - lo + 1;                 // 32, or 31 for s=15

    const long base = (long)b * (T_DIM * D_DIM) + d0;
    const float* pr  = R   + base + (long)hi * D_DIM;
    const float* pq  = Q   + base + (long)hi * D_DIM;
    const float* pe  = E   + base + (long)(hi + 1) * D_DIM;
    const float* ptq = TQ  + base + (long)(hi + 1) * D_DIM;
    const float* ptp = TPP + base + (long)(hi + 1) * D_DIM;
    const float* pb  = BPP + (long)b * T_DIM + (hi + 1);

    float4 A   = make_float4(1.f, 1.f, 1.f, 1.f);
    float4 Bv  = make_float4(0.f, 0.f, 0.f, 0.f);
    float4 sAA = Bv, sAd = Bv, sdd = Bv;

    int i = 0;
    for (; i + 2 <= n; i += 2) {
        const int o0 = i * D_DIM, o1 = (i + 1) * D_DIM;
        // Issue all 10 vector loads (+2 scalars) before the dependent chains.
        float4 r0  = *(const float4*)(pr  - o0), r1  = *(const float4*)(pr  - o1);
        float4 q0  = *(const float4*)(pq  - o0), q1  = *(const float4*)(pq  - o1);
        float4 e0  = *(const float4*)(pe  - o0), e1  = *(const float4*)(pe  - o1);
        float4 t0  = *(const float4*)(ptq - o0), t1  = *(const float4*)(ptq - o1);
        float4 p0  = *(const float4*)(ptp - o0), p1  = *(const float4*)(ptp - o1);
        float  b0  = pb[-i], b1 = pb[-(i + 1)];
        step4(r0, q0, e0, t0, p0, b0, A, Bv, sAA, sAd, sdd);
        step4(r1, q1, e1, t1, p1, b1, A, Bv, sAA, sAd, sdd);
    }
    if (i < n) {                                // odd tail (s=15)
        const int o = i * D_DIM;
        step4(*(const float4*)(pr - o),  *(const float4*)(pq - o),
              *(const float4*)(pe - o),  *(const float4*)(ptq - o),
              *(const float4*)(ptp - o), pb[-i],
              A, Bv, sAA, sAd, sdd);
    }

    const int idx = s * NCHAINS + cg * 4;       // consecutive threads -> consecutive float4
    *(float4*)(g_sAA + idx) = sAA;
    *(float4*)(g_sAd + idx) = sAd;
    *(float4*)(g_sdd + idx) = sdd;
    *(float4*)(g_A   + idx) = A;
    *(float4*)(g_B   + idx) = Bv;
}

// ------------- Phase 2: chain segments, reduce, finalize (fused) -------------
__global__ __launch_bounds__(BLOCK)
void retrace_combine(const float* __restrict__ TQ,
                     float* __restrict__ out,
                     double inv_count)
{
    const int cid = blockIdx.x * BLOCK + threadIdx.x;
    const int b = cid >> 4;
    const int d = cid & 15;

    // x = target_Q[:, -1]
    float x = TQ[(long)b * (T_DIM * D_DIM) + (long)(T_DIM - 1) * D_DIM + d];

    float loss = 0.0f;
    #pragma unroll
    for (int s = SEG - 1; s >= 0; --s) {        // latest times first
        const int idx = s * NCHAINS + cid;
        const float aa = g_sAA[idx];
        const float ad = g_sAd[idx];
        const float dd = g_sdd[idx];
        const float A  = g_A[idx];
        const float Bv = g_B[idx];
        loss += fmaf(x, fmaf(x, aa, -2.0f * ad), dd);
        x = fmaf(A, x, Bv);
    }

    // Deterministic block reduction.
    #pragma unroll
    for (int off = 16; off > 0; off >>= 1)
        loss += __shfl_xor_sync(0xFFFFFFFFu, loss, off);

    __shared__ float s_warp[BLOCK / 32];
    const int lane = threadIdx.x & 31;
    const int wid  = threadIdx.x >> 5;
    if (lane == 0) s_warp[wid] = loss;
    __syncthreads();

    __shared__ bool s_last;
    if (threadIdx.x == 0) {
        g_partials[blockIdx.x] = s_warp[0] + s_warp[1] + s_warp[2] + s_warp[3];
        __threadfence();
        unsigned int t = atomicAdd(&g_ticket, 1u);
        s_last = (t == NBLK2 - 1);
    }
    __syncthreads();

    if (s_last) {
        __shared__ double s_d[BLOCK];
        double v = 0.0;
        for (int i = threadIdx.x; i < NBLK2; i += BLOCK)
            v += (double)g_partials[i];
        s_d[threadIdx.x] = v;
        __syncthreads();
        for (int stride = BLOCK >> 1; stride > 0; stride >>= 1) {
            if (threadIdx.x < stride) s_d[threadIdx.x] += s_d[threadIdx.x + stride];
            __syncthreads();
        }
        if (threadIdx.x == 0) {
            out[0] = (float)(s_d[0] * inv_count);
            g_ticket = 0;                       // reset for next graph replay
        }
    }
}

extern "C" void kernel_launch(void* const* d_in, const int* in_sizes, int n_in,
                              void* d_out, int out_size)
{
    const float* Q   = (const float*)d_in[0];
    const float* E   = (const float*)d_in[1];
    const float* TQ  = (const float*)d_in[2];
    const float* R   = (const float*)d_in[3];
    const float* TPP = (const float*)d_in[4];
    const float* BPP = (const float*)d_in[5];

    const int B = in_sizes[5] / T_DIM;          // 2048
    const double inv_count =
        1.0 / ((double)B * (double)(T_DIM - 1) * (double)D_DIM);

    retrace_seg<<<NBLK1, BLOCK>>>(Q, E, TQ, R, TPP, BPP);
    retrace_combine<<<NBLK2, BLOCK>>>(TQ, (float*)d_out, inv_count);
}

// round 8
// speedup vs baseline: 1.4120x; 1.4120x over previous
#include <cuda_runtime.h>

// Retrace: B=2048, T=512, D=16 (fp32).
// Segmented affine scan (scalar, one thread per (chain, segment)):
//   segment summary: carry_out = A*x + B,  loss_seg(x) = sdd - 2x*sAd + x^2*sAA
// Phase 2 chains segments (x <- A*x + B), sums quadratics, reduces to the mean.
// Grid shaped to a SINGLE balanced wave: 1024 blocks x 128 thr, regs capped at 64.
//
// Inputs (metadata order):
//   0: Q [B,T,D]  1: expected_target_Q [B,T,D]  2: target_Q [B,T,D]
//   3: rewards [B,T,D]  4: target_policy_probs [B,T,D]  5: behaviour_policy_probs [B,T]
// Output: scalar fp32 = mean((Q[:, :-1] - q_ret)^2)

#define T_DIM 512
#define D_DIM 16
#define GAMMA 0.99f
#define BLOCK 128
#define SEG 4
#define SEGLEN 128                      // 511 = 4*128 - 1 (last segment: 127 steps)
#define NCHAINS (2048 * 16)             // 32768
#define NBLK1 ((NCHAINS * SEG) / BLOCK) // 1024  (single wave at occ >= 7/SM)
#define NBLK2 (NCHAINS / BLOCK)         // 256
#define GROUP 4

__device__ float g_sAA[SEG * NCHAINS];
__device__ float g_sAd[SEG * NCHAINS];
__device__ float g_sdd[SEG * NCHAINS];
__device__ float g_A  [SEG * NCHAINS];
__device__ float g_B  [SEG * NCHAINS];
__device__ float g_partials[NBLK2];
__device__ unsigned int g_ticket;       // zero-init; reset by finalizer each launch

// ---------------- Phase 1: per-(chain, segment) affine summary ----------------
__global__ __launch_bounds__(BLOCK, 8)   // cap regs at 64 -> occ_lim 8 blocks/SM
void retrace_seg(const float* __restrict__ Q,
                 const float* __restrict__ E,
                 const float* __restrict__ TQ,
                 const float* __restrict__ R,
                 const float* __restrict__ TPP,
                 const float* __restrict__ BPP)
{
    const int tid = blockIdx.x * BLOCK + threadIdx.x;
    const int cid = tid & (NCHAINS - 1);     // chain id (d fastest -> coalesced)
    const int s   = tid >> 15;               // segment id, 0..3
    const int b   = cid >> 4;
    const int d   = cid & 15;

    const int lo = s * SEGLEN;
    const int hi = (s == SEG - 1) ? (T_DIM - 2) : (lo + SEGLEN - 1);
    const int n  = hi - lo + 1;              // 128, or 127 for s=3

    const long base = (long)b * (T_DIM * D_DIM) + d;
    const float* pr  = R   + base + (long)hi * D_DIM;        // rewards[t]
    const float* pq  = Q   + base + (long)hi * D_DIM;        // Q[t]
    const float* pe  = E   + base + (long)(hi + 1) * D_DIM;  // E[t+1]
    const float* ptq = TQ  + base + (long)(hi + 1) * D_DIM;  // TQ[t+1]
    const float* ptp = TPP + base + (long)(hi + 1) * D_DIM;  // TPP[t+1]
    const float* pb  = BPP + (long)b * T_DIM + (hi + 1);     // BPP[t+1]

    // carry = A*x + B over the segment; loss quadratic accumulators.
    float A = 1.0f, Bv = 0.0f;
    float sAA = 0.0f, sAd = 0.0f, sdd = 0.0f;

    int i = 0;
    for (; i + GROUP <= n; i += GROUP) {
        float r[GROUP], qv[GROUP], e[GROUP], tq[GROUP], tp[GROUP], bp[GROUP];
        #pragma unroll
        for (int k = 0; k < GROUP; ++k) {
            const int o = (i + k) * D_DIM;
            r[k]  = pr [-o];
            qv[k] = pq [-o];
            e[k]  = pe [-o];
            tq[k] = ptq[-o];
            tp[k] = ptp[-o];
            bp[k] = pb [-(i + k)];
        }
        #pragma unroll
        for (int k = 0; k < GROUP; ++k) {
            float c  = __expf(fminf(tp[k] - bp[k], 0.0f));
            float m  = GAMMA * c;
            float t1 = fmaf(GAMMA, e[k], r[k]);      // r + g*e
            Bv = fmaf(m, Bv - tq[k], t1);            // B' = m*(B - tq) + r + g*e
            A  = m * A;                              // A' = m*A
            float dv = qv[k] - Bv;                   // df = dv - A'*x
            sdd = fmaf(dv, dv, sdd);
            sAd = fmaf(A, dv, sAd);
            sAA = fmaf(A, A, sAA);
        }
    }
    for (; i < n; ++i) {                             // remainder (3 steps for s=3)
        const int o = i * D_DIM;
        float c  = __expf(fminf(ptp[-o] - pb[-i], 0.0f));
        float m  = GAMMA * c;
        float t1 = fmaf(GAMMA, pe[-o], pr[-o]);
        Bv = fmaf(m, Bv - ptq[-o], t1);
        A  = m * A;
        float dv = pq[-o] - Bv;
        sdd = fmaf(dv, dv, sdd);
        sAd = fmaf(A, dv, sAd);
        sAA = fmaf(A, A, sAA);
    }

    const int idx = s * NCHAINS + cid;               // [seg][chain] -> phase-2 coalesced
    g_sAA[idx] = sAA;
    g_sAd[idx] = sAd;
    g_sdd[idx] = sdd;
    g_A[idx]   = A;
    g_B[idx]   = Bv;
}

// ------------- Phase 2: chain segments, reduce, finalize (fused) -------------
__global__ __launch_bounds__(BLOCK, 1)   // allow many regs -> front-batch all loads
void retrace_combine(const float* __restrict__ TQ,
                     float* __restrict__ out,
                     double inv_count)
{
    const int cid = blockIdx.x * BLOCK + threadIdx.x;
    const int b = cid >> 4;
    const int d = cid & 15;

    // Load EVERYTHING first (independent), then run the dependent chain.
    float aa[SEG], ad[SEG], dd[SEG], Av[SEG], Bs[SEG];
    #pragma unroll
    for (int s = 0; s < SEG; ++s) {
        const int idx = s * NCHAINS + cid;
        aa[s] = g_sAA[idx];
        ad[s] = g_sAd[idx];
        dd[s] = g_sdd[idx];
        Av[s] = g_A[idx];
        Bs[s] = g_B[idx];
    }
    float x = TQ[(long)b * (T_DIM * D_DIM) + (long)(T_DIM - 1) * D_DIM + d];

    float loss = 0.0f;
    #pragma unroll
    for (int s = SEG - 1; s >= 0; --s) {             // latest times first
        loss += fmaf(x, fmaf(x, aa[s], -2.0f * ad[s]), dd[s]);
        x = fmaf(Av[s], x, Bs[s]);
    }

    // Deterministic block reduction.
    #pragma unroll
    for (int off = 16; off > 0; off >>= 1)
        loss += __shfl_xor_sync(0xFFFFFFFFu, loss, off);

    __shared__ float s_warp[BLOCK / 32];
    const int lane = threadIdx.x & 31;
    const int wid  = threadIdx.x >> 5;
    if (lane == 0) s_warp[wid] = loss;
    __syncthreads();

    __shared__ bool s_last;
    if (threadIdx.x == 0) {
        g_partials[blockIdx.x] = s_warp[0] + s_warp[1] + s_warp[2] + s_warp[3];
        __threadfence();
        unsigned int t = atomicAdd(&g_ticket, 1u);
        s_last = (t == NBLK2 - 1);
    }
    __syncthreads();

    if (s_last) {
        __shared__ double s_d[BLOCK];
        double v = 0.0;
        for (int i = threadIdx.x; i < NBLK2; i += BLOCK)
            v += (double)g_partials[i];
        s_d[threadIdx.x] = v;
        __syncthreads();
        for (int stride = BLOCK >> 1; stride > 0; stride >>= 1) {
            if (threadIdx.x < stride) s_d[threadIdx.x] += s_d[threadIdx.x + stride];
            __syncthreads();
        }
        if (threadIdx.x == 0) {
            out[0] = (float)(s_d[0] * inv_count);
            g_ticket = 0;                            // reset for next graph replay
        }
    }
}

extern "C" void kernel_launch(void* const* d_in, const int* in_sizes, int n_in,
                              void* d_out, int out_size)
{
    const float* Q   = (const float*)d_in[0];
    const float* E   = (const float*)d_in[1];
    const float* TQ  = (const float*)d_in[2];
    const float* R   = (const float*)d_in[3];
    const float* TPP = (const float*)d_in[4];
    const float* BPP = (const float*)d_in[5];

    const int B = in_sizes[5] / T_DIM;               // 2048
    const double inv_count =
        1.0 / ((double)B * (double)(T_DIM - 1) * (double)D_DIM);

    retrace_seg<<<NBLK1, BLOCK>>>(Q, E, TQ, R, TPP, BPP);
    retrace_combine<<<NBLK2, BLOCK>>>(TQ, (float*)d_out, inv_count);
}